// round 11
// baseline (speedup 1.0000x reference)
#include <cuda_runtime.h>

#define H 2048
#define S 8192
#define EB 512               // k_energy blocks; all resident at 4/SM (4*148=592)

// Scratch (no allocs allowed). g_u starts zero (static init); k_energy
// re-zeros it each invocation after the grid barrier, so "g_u == 0 on entry"
// holds for the correctness run, the capture, and every graph replay.
__device__ float    g_u[H];
__device__ float    g_mb[EB];
__device__ float    g_zb[EB];
__device__ unsigned g_count = 0;   // barrier arrival counter (self-resetting)
__device__ unsigned g_gen   = 0;   // barrier generation (monotonic across replays)

// ---------------------------------------------------------------------------
// Kernel 1: u[j] += sum over a 16-row i-chunk of h[i] * W[i, j]
// Grid (H/256, 128) = 1024 blocks (~7/SM). Fully unrolled, scalar coalesced.
// (Proven R9: 7.8us cold, ~2.5us warm.)
// ---------------------------------------------------------------------------
#define ICHUNKS 128
#define IROWS   (H / ICHUNKS)     // 16

__global__ void k_compute_u(const float* __restrict__ h,
                            const float* __restrict__ W) {
    const int j  = blockIdx.x * blockDim.x + threadIdx.x;
    const int i0 = blockIdx.y * IROWS;

    float acc = 0.0f;
#pragma unroll
    for (int r = 0; r < IROWS; ++r) {
        const int i = i0 + r;
        acc = fmaf(__ldg(h + i), W[(size_t)i * H + j], acc);
    }
    atomicAdd(&g_u[j], acc);
}

// ---------------------------------------------------------------------------
// Grid barrier across EB blocks (all resident via __launch_bounds__(256,4)).
// Monotonic generation counter -> graph-replay safe.
// ---------------------------------------------------------------------------
__device__ __forceinline__ void grid_barrier() {
    __syncthreads();
    __threadfence();
    if (threadIdx.x == 0) {
        unsigned gen0 = *(volatile unsigned*)&g_gen;
        if (atomicAdd(&g_count, 1u) == EB - 1) {
            g_count = 0;
            __threadfence();
            atomicAdd(&g_gen, 1u);         // release
        } else {
            while (*(volatile unsigned*)&g_gen == gen0) { }
        }
        __threadfence();                   // acquire
    }
    __syncthreads();
}

// ---------------------------------------------------------------------------
// Kernel 2: energies + softmax (fused, one balanced grid barrier).
// QUARTER-ROW layout for occupancy: warp w of a block owns column-quarter
// q = w&3 (512 floats) of row-group g = w>>2 (8 rows). Each lane caches just
// 4 float4 of u (16 regs) -> ~56 regs/thread -> 4 blocks/SM (32 warps, 2x R10
// occupancy). Per-row quarter-partials meet in smem, energies -> (m_b, z_b).
// Barrier. Phase B: every block redundantly reduces all 512 (m,z) pairs
// (L2-hot) to (M, 1/Z), normalizes its OWN 16 energies from smem.
// ---------------------------------------------------------------------------
__global__ __launch_bounds__(256, 4)
void k_energy(const float* __restrict__ enc, float* __restrict__ out) {
    __shared__ float sP[16][4];        // [row][quarter] partials
    __shared__ float sE[16];
    __shared__ float sM, sInvZ;

    const int tid  = threadIdx.x;
    const int wid  = tid >> 5;         // 0..7
    const int lane = tid & 31;
    const int q    = wid & 3;          // column quarter
    const int g    = wid >> 2;         // row group (0/1)

    // ---- Phase A: cache this warp's u quarter in registers (16 regs) ----
    const float4* uv = reinterpret_cast<const float4*>(g_u) + q * 128;
    float4 u[4];
#pragma unroll
    for (int k = 0; k < 4; ++k)
        u[k] = uv[lane + k * 32];

    const int s0 = blockIdx.x * 16 + g * 8;

#pragma unroll
    for (int r = 0; r < 8; ++r) {
        const float4* row =
            reinterpret_cast<const float4*>(enc + (size_t)(s0 + r) * H) + q * 128;
        float acc = 0.0f;
#pragma unroll
        for (int k = 0; k < 4; ++k) {
            float4 v = row[lane + k * 32];
            acc = fmaf(v.x, u[k].x, acc);
            acc = fmaf(v.y, u[k].y, acc);
            acc = fmaf(v.z, u[k].z, acc);
            acc = fmaf(v.w, u[k].w, acc);
        }
#pragma unroll
        for (int off = 16; off; off >>= 1)
            acc += __shfl_xor_sync(0xFFFFFFFFu, acc, off);
        if (lane == 0) sP[g * 8 + r][q] = acc;
    }
    __syncthreads();

    // Combine quarters -> 16 energies; block-local (m, z). Warp 0 only.
    if (wid == 0) {
        float e = -1e30f;
        if (lane < 16) {
            e = sP[lane][0] + sP[lane][1] + sP[lane][2] + sP[lane][3];
            sE[lane] = e;
        }
        float m = e;
#pragma unroll
        for (int off = 16; off; off >>= 1)
            m = fmaxf(m, __shfl_xor_sync(0xFFFFFFFFu, m, off));
        float z = (lane < 16) ? __expf(e - m) : 0.0f;
#pragma unroll
        for (int off = 16; off; off >>= 1)
            z += __shfl_xor_sync(0xFFFFFFFFu, z, off);
        if (lane == 0) { g_mb[blockIdx.x] = m; g_zb[blockIdx.x] = z; }
    }

    grid_barrier();   // all (m_b, z_b) visible; all u reads complete

    // ---- Phase B: global (M, 1/Z), redundant per block ----
    if (tid < 32) {
        float m = -1e30f;
#pragma unroll
        for (int i = 0; i < EB / 32; ++i)
            m = fmaxf(m, g_mb[lane + i * 32]);
#pragma unroll
        for (int off = 16; off; off >>= 1)
            m = fmaxf(m, __shfl_xor_sync(0xFFFFFFFFu, m, off));
        float z = 0.0f;
#pragma unroll
        for (int i = 0; i < EB / 32; ++i)
            z += g_zb[lane + i * 32] * __expf(g_mb[lane + i * 32] - m);
#pragma unroll
        for (int off = 16; off; off >>= 1)
            z += __shfl_xor_sync(0xFFFFFFFFu, z, off);
        if (lane == 0) { sM = m; sInvZ = 1.0f / z; }
    }
    __syncthreads();

    // Normalize this block's 16 energies (still in smem) -> out.
    if (tid < 16)
        out[blockIdx.x * 16 + tid] = __expf(sE[tid] - sM) * sInvZ;

    // Restore g_u == 0 invariant (u consumed before the barrier).
    if (blockIdx.x < 8)
        g_u[blockIdx.x * 256 + tid] = 0.0f;
}

// ---------------------------------------------------------------------------
// Launch. Inputs: hidden[2048], encoder_outputs[8192*2048], W[2048*2048],
// b[2048] (zero + softmax-invariant -> ignored). Output: 8192 floats.
// ---------------------------------------------------------------------------
extern "C" void kernel_launch(void* const* d_in, const int* in_sizes, int n_in,
                              void* d_out, int out_size) {
    const float* hidden = (const float*)d_in[0];
    const float* enc    = (const float*)d_in[1];
    const float* W      = (const float*)d_in[2];
    float* out          = (float*)d_out;

    dim3 g1(H / 256, ICHUNKS);   // (8, 128) = 1024 blocks
    k_compute_u<<<g1, 256>>>(hidden, W);

    k_energy<<<EB, 256>>>(enc, out);
}